// round 1
// baseline (speedup 1.0000x reference)
#include <cuda_runtime.h>

// DeconvCapsuleLayer fused kernel:
//   conv2d_transpose (k=4, s=2, SAME, TF semantics via transpose_kernel=True)
//   + 3-iteration capsule routing (softmax over cout, squash over atoms),
// all fused so the [B,Cin,112,112,8,16] votes tensor never touches HBM.
//
// Reference quirk reproduced: conv batch is Cin-major ([Cin*B,...]) but votes
// are reshaped (B, Cin, ...), so route i of output batch b uses input
// (bb, cin) = ((8b+i)&3, (8b+i)>>2).

namespace {
constexpr int HIN = 56, WIN = 56, CIN = 8, AIN = 32;
constexpr int HP = 112, WP = 112;
constexpr int CA = 128;   // Cout(8) * Aout(16)
constexpr int KD = 128;   // 4 taps * 32 ain
}

// Per-parity-class weights: [class(4)][k = tap*32+ain (128)][ca (128)]
__device__ float g_Wc[4 * KD * CA];

__global__ void prep_weights_kernel(const float* __restrict__ W) {
    int idx = blockIdx.x * blockDim.x + threadIdx.x;
    if (idx >= 4 * KD * CA) return;
    int ca   = idx & 127;
    int k    = (idx >> 7) & 127;
    int cls  = idx >> 14;
    int t    = k >> 5;       // tap = pp*2 + qq
    int ain  = k & 31;
    int hpar = cls >> 1, wpar = cls & 1;
    int p = (1 - hpar) + 2 * (t >> 1);
    int q = (1 - wpar) + 2 * (t & 1);
    // W layout: [p(4)][q(4)][ca(128)][ain(32)]
    g_Wc[idx] = W[((p * 4 + q) * CA + ca) * AIN + ain];
}

__global__ void __launch_bounds__(256)
deconv_caps_kernel(const float* __restrict__ x,
                   const float* __restrict__ bias,
                   float* __restrict__ out)
{
    // One warp = one output pixel. 8 warps/block share (b, h, wpar) -> same class.
    __shared__ float Xsh[8 * 1024];   // per warp: [route(8)][k(128)]

    const int lane = threadIdx.x & 31;
    const int warp = threadIdx.x >> 5;
    const int h    = blockIdx.y;
    const int b    = blockIdx.z;
    const int wpar = blockIdx.x & 1;
    const int wblk = blockIdx.x >> 1;
    const int w    = wpar + 2 * (wblk * 8 + warp);      // 0..111, parity = wpar
    const int cls  = (h & 1) * 2 + wpar;
    const int ih   = (h + 1) >> 1;
    const int jw   = (w + 1) >> 1;

    // ---- gather x for this pixel: Xsh[warp][route][tap*32+ain], 0-padded OOB taps
    float4* Xw4 = (float4*)(Xsh + warp * 1024);
    {
        const int t  = lane >> 3;          // tap for this lane
        const int a4 = lane & 7;           // float4 index within 32 ain
        const int ii = ih - (t >> 1);
        const int jj = jw - (t & 1);
        const bool valid = ((unsigned)ii < (unsigned)HIN) && ((unsigned)jj < (unsigned)WIN);
        #pragma unroll
        for (int r = 0; r < 8; ++r) {
            int n   = b * 8 + r;           // reference reshape quirk
            int bb  = n & 3;
            int cin = n >> 2;
            float4 v = make_float4(0.f, 0.f, 0.f, 0.f);
            if (valid) {
                const float4* src = (const float4*)x
                    + ((((bb * HIN + ii) * WIN + jj) * CIN + cin) * AIN >> 2);
                v = __ldg(src + a4);
            }
            Xw4[r * 32 + lane] = v;        // float4 index = r*32 + t*8 + a4  (k-contiguous)
        }
    }
    __syncwarp();

    // ---- votes GEMM: acc[route][j], lane owns columns ca = 4*lane + j
    float acc[8][4];
    #pragma unroll
    for (int i = 0; i < 8; ++i) {
        acc[i][0] = 0.f; acc[i][1] = 0.f; acc[i][2] = 0.f; acc[i][3] = 0.f;
    }

    const float4* __restrict__ W4 = (const float4*)(g_Wc + cls * (KD * CA));
    #pragma unroll 2
    for (int k4 = 0; k4 < 32; ++k4) {
        float4 w0 = __ldg(W4 + (k4 * 4 + 0) * 32 + lane);
        float4 w1 = __ldg(W4 + (k4 * 4 + 1) * 32 + lane);
        float4 w2 = __ldg(W4 + (k4 * 4 + 2) * 32 + lane);
        float4 w3 = __ldg(W4 + (k4 * 4 + 3) * 32 + lane);
        #pragma unroll
        for (int i = 0; i < 8; ++i) {
            float4 xv = Xw4[i * 32 + k4];  // broadcast LDS.128
            acc[i][0] = fmaf(xv.x, w0.x, acc[i][0]);
            acc[i][1] = fmaf(xv.x, w0.y, acc[i][1]);
            acc[i][2] = fmaf(xv.x, w0.z, acc[i][2]);
            acc[i][3] = fmaf(xv.x, w0.w, acc[i][3]);
            acc[i][0] = fmaf(xv.y, w1.x, acc[i][0]);
            acc[i][1] = fmaf(xv.y, w1.y, acc[i][1]);
            acc[i][2] = fmaf(xv.y, w1.z, acc[i][2]);
            acc[i][3] = fmaf(xv.y, w1.w, acc[i][3]);
            acc[i][0] = fmaf(xv.z, w2.x, acc[i][0]);
            acc[i][1] = fmaf(xv.z, w2.y, acc[i][1]);
            acc[i][2] = fmaf(xv.z, w2.z, acc[i][2]);
            acc[i][3] = fmaf(xv.z, w2.w, acc[i][3]);
            acc[i][0] = fmaf(xv.w, w3.x, acc[i][0]);
            acc[i][1] = fmaf(xv.w, w3.y, acc[i][1]);
            acc[i][2] = fmaf(xv.w, w3.z, acc[i][2]);
            acc[i][3] = fmaf(xv.w, w3.w, acc[i][3]);
        }
    }

    // ---- routing (3 iterations), all in registers + shuffles.
    // lane's 4 columns all belong to cout c = lane>>2; a = 4*(lane&3)+j.
    const float4 bs = __ldg((const float4*)bias + lane);

    float logits[8];
    #pragma unroll
    for (int i = 0; i < 8; ++i) logits[i] = 0.f;

    float a0 = 0.f, a1 = 0.f, a2 = 0.f, a3 = 0.f;  // act for lane's 4 atoms

    #pragma unroll
    for (int it = 0; it < 3; ++it) {
        // softmax over the 8 couts (replicated within each 4-lane a-group,
        // so xor {4,8,16} reduces exactly over cout)
        float r[8];
        #pragma unroll
        for (int i = 0; i < 8; ++i) {
            float m = logits[i];
            m = fmaxf(m, __shfl_xor_sync(0xffffffffu, m, 4));
            m = fmaxf(m, __shfl_xor_sync(0xffffffffu, m, 8));
            m = fmaxf(m, __shfl_xor_sync(0xffffffffu, m, 16));
            float e = expf(logits[i] - m);
            float s = e;
            s += __shfl_xor_sync(0xffffffffu, s, 4);
            s += __shfl_xor_sync(0xffffffffu, s, 8);
            s += __shfl_xor_sync(0xffffffffu, s, 16);
            r[i] = e / s;
        }
        // pre = bias + sum_i r[i]*votes[i]
        float p0 = bs.x, p1 = bs.y, p2 = bs.z, p3 = bs.w;
        #pragma unroll
        for (int i = 0; i < 8; ++i) {
            p0 = fmaf(r[i], acc[i][0], p0);
            p1 = fmaf(r[i], acc[i][1], p1);
            p2 = fmaf(r[i], acc[i][2], p2);
            p3 = fmaf(r[i], acc[i][3], p3);
        }
        // squash: norm over the 16 atoms of this cout (xor {1,2} over a-group)
        float sq = p0 * p0 + p1 * p1 + p2 * p2 + p3 * p3;
        sq += __shfl_xor_sync(0xffffffffu, sq, 1);
        sq += __shfl_xor_sync(0xffffffffu, sq, 2);
        float scale = sq / ((1.0f + sq) * sqrtf(sq + 1e-9f));
        a0 = p0 * scale; a1 = p1 * scale; a2 = p2 * scale; a3 = p3 * scale;

        if (it < 2) {
            #pragma unroll
            for (int i = 0; i < 8; ++i) {
                float d = acc[i][0] * a0 + acc[i][1] * a1
                        + acc[i][2] * a2 + acc[i][3] * a3;
                d += __shfl_xor_sync(0xffffffffu, d, 1);
                d += __shfl_xor_sync(0xffffffffu, d, 2);
                logits[i] += d;
            }
        }
    }

    // ---- write act: out[b,h,w,ca], float4 per lane (coalesced 512B per warp)
    ((float4*)out)[(size_t)((b * HP + h) * WP + w) * 32 + lane]
        = make_float4(a0, a1, a2, a3);
}

extern "C" void kernel_launch(void* const* d_in, const int* in_sizes, int n_in,
                              void* d_out, int out_size) {
    const float* x = nullptr;
    const float* W = nullptr;
    const float* bias = nullptr;
    for (int i = 0; i < n_in; ++i) {
        if (in_sizes[i] == 4 * 56 * 56 * 8 * 32) x    = (const float*)d_in[i];
        else if (in_sizes[i] == 4 * 4 * 128 * 32) W   = (const float*)d_in[i];
        else if (in_sizes[i] == 128)              bias = (const float*)d_in[i];
    }
    float* out = (float*)d_out;

    prep_weights_kernel<<<(4 * KD * CA + 255) / 256, 256>>>(W);

    // grid: x = (wblk(7) * 2 + wpar) = 14, y = h (112), z = b (4)
    dim3 grid(14, HP, 4);
    deconv_caps_kernel<<<grid, 256>>>(x, bias, out);
}